// round 5
// baseline (speedup 1.0000x reference)
#include <cuda_runtime.h>

#define NB   32768
#define PP   32
#define NCC  33
#define NBLK 512   // 2 sides x 256 item-blocks

__device__ float g_partials[NBLK];
__device__ int   g_count;   // zero-init; reset by finishing block each launch

typedef unsigned long long ull;

__device__ __forceinline__ ull ffma2(ull a, ull b, ull c) {
    ull d; asm("fma.rn.f32x2 %0, %1, %2, %3;" : "=l"(d) : "l"(a), "l"(b), "l"(c)); return d;
}
__device__ __forceinline__ ull fadd2(ull a, ull b) {
    ull d; asm("add.rn.f32x2 %0, %1, %2;" : "=l"(d) : "l"(a), "l"(b)); return d;
}
__device__ __forceinline__ ull fmul2(ull a, ull b) {
    ull d; asm("mul.rn.f32x2 %0, %1, %2;" : "=l"(d) : "l"(a), "l"(b)); return d;
}
__device__ __forceinline__ ull pack2(float lo, float hi) {
    ull d; asm("mov.b64 %0, {%1, %2};" : "=l"(d) : "f"(lo), "f"(hi)); return d;
}
__device__ __forceinline__ float2 unpack2(ull v) {
    float2 r; asm("mov.b64 {%0, %1}, %2;" : "=f"(r.x), "=f"(r.y) : "l"(v)); return r;
}

// Cross-entropy from a shared-memory row (stride-33 => conflict-free).
__device__ __forceinline__ float ce_smem(const float* __restrict__ row, int tgt, int* amax_out) {
    float m = -1e30f; int amax = 0;
#pragma unroll
    for (int j = 0; j < NCC; j++) {
        float x = row[j];
        if (x > m) { m = x; amax = j; }
    }
    float s = 0.f;
#pragma unroll
    for (int j = 0; j < NCC; j++)
        s += __expf(row[j] - m);
    *amax_out = amax;
    return m + __logf(s) - row[tgt];
}

// Chamfer with DIRECT squared differences (accuracy-safe): two targets packed
// per f32x2 register, two pred points per unrolled step. Pred loads batched
// 4x LDG.128 per chunk (MLP=4); latency hidden by 16 warps/SM occupancy.
__device__ __forceinline__ float chamfer(const float4* __restrict__ pred4,
                                         const float4* __restrict__ tgt4,
                                         int np, int nt) {
    // Targets (negated, packed); invalid -> -(+1e18). Fully unrolled: 16
    // batched LDG.128 (MLP=16), a single latency exposure.
    ull TX[PP / 2], TY[PP / 2];
    float sum_tsq = 0.f;
#pragma unroll
    for (int j = 0; j < PP / 2; j++) {
        float4 t = __ldg(tgt4 + j);
        float x0, y0, x1, y1;
        if (2 * j < nt)     { sum_tsq += t.x * t.x + t.y * t.y; x0 = -t.x; y0 = -t.y; }
        else                { x0 = -1e18f; y0 = -1e18f; }
        if (2 * j + 1 < nt) { sum_tsq += t.z * t.z + t.w * t.w; x1 = -t.z; y1 = -t.w; }
        else                { x1 = -1e18f; y1 = -1e18f; }
        TX[j] = pack2(x0, x1); TY[j] = pack2(y0, y1);
    }

    float mintlo[PP / 2], minthi[PP / 2];
#pragma unroll
    for (int j = 0; j < PP / 2; j++) { mintlo[j] = 1e30f; minthi[j] = 1e30f; }

    float sum_minp = 0.f, sum_psq = 0.f;

#pragma unroll 1
    for (int c = 0; c < 4; c++) {
        // 4 batched LDG.128 (8 pred points), then compute.
        float4 cur0 = __ldg(pred4 + 4 * c + 0);
        float4 cur1 = __ldg(pred4 + 4 * c + 1);
        float4 cur2 = __ldg(pred4 + 4 * c + 2);
        float4 cur3 = __ldg(pred4 + 4 * c + 3);
#pragma unroll
        for (int u = 0; u < 4; u++) {
            const int i = 4 * c + u;
            float4 p = (u == 0) ? cur0 : (u == 1) ? cur1 : (u == 2) ? cur2 : cur3;
            const bool va = (2 * i < np), vb = (2 * i + 1 < np);
            float ax = p.x, ay = p.y, bx = p.z, by = p.w;
            if (va) sum_psq += ax * ax + ay * ay; else { ax = -1e18f; ay = -1e18f; }
            if (vb) sum_psq += bx * bx + by * by; else { bx = -1e18f; by = -1e18f; }

            const ull AX = pack2(ax, ax), AY = pack2(ay, ay);
            const ull BX = pack2(bx, bx), BY = pack2(by, by);

            float mina = 1e30f, minb = 1e30f;
#pragma unroll
            for (int j = 0; j < PP / 2; j++) {
                ull dxa = fadd2(AX, TX[j]);
                ull dya = fadd2(AY, TY[j]);
                ull da  = ffma2(dxa, dxa, fmul2(dya, dya));
                ull dxb = fadd2(BX, TX[j]);
                ull dyb = fadd2(BY, TY[j]);
                ull db  = ffma2(dxb, dxb, fmul2(dyb, dyb));
                float2 daf = unpack2(da), dbf = unpack2(db);
                mina = fminf(mina, fminf(daf.x, daf.y));
                minb = fminf(minb, fminf(dbf.x, dbf.y));
                mintlo[j] = fminf(mintlo[j], fminf(daf.x, dbf.x));
                minthi[j] = fminf(minthi[j], fminf(daf.y, dbf.y));
            }
            if (va) sum_minp += mina;
            if (vb) sum_minp += minb;
        }
    }

    float sum_mint = 0.f;
#pragma unroll
    for (int j = 0; j < PP / 2; j++) {
        if (2 * j < nt)     sum_mint += mintlo[j];
        if (2 * j + 1 < nt) sum_mint += minthi[j];
    }

    if (np == 0 && nt == 0) return 0.f;
    if (np == 0) return sum_tsq;
    if (nt == 0) return sum_psq;
    return sum_minp / (float)np + sum_mint / (float)nt;
}

// Each block handles 128 items on ONE side (poles or zeros):
//   side = blockIdx.x & 1, item-block = blockIdx.x >> 1.
__global__ __launch_bounds__(128, 4)
void loss_kernel(const float*  __restrict__ pole_logits,
                 const float*  __restrict__ zero_logits,
                 const float4* __restrict__ poles,
                 const float4* __restrict__ zeros,
                 const float4* __restrict__ tpoles,
                 const float4* __restrict__ tzeros,
                 const int*    __restrict__ tnp,
                 const int*    __restrict__ tnz,
                 float*        __restrict__ out) {
    __shared__ __align__(16) float slog[128 * NCC];   // 16896 B
    __shared__ float sred[128];
    __shared__ int   sflag;

    const int tid  = threadIdx.x;
    const int side = blockIdx.x & 1;
    const int ib   = blockIdx.x >> 1;
    const int b    = ib * 128 + tid;

    const float*  logits = side ? zero_logits : pole_logits;
    const float4* pred   = side ? zeros       : poles;
    const float4* tgt    = side ? tzeros      : tpoles;
    const int*    tn     = side ? tnz         : tnp;

    // Coalesced float4 staging, fully unrolled => MLP ~ 9.
    {
        const float4* src = (const float4*)(logits + (size_t)ib * 128 * NCC);
        float4* dst = (float4*)slog;
#pragma unroll
        for (int k = 0; k < 8; k++)
            dst[tid + 128 * k] = __ldg(src + tid + 128 * k);
        if (tid < 32)
            dst[1024 + tid] = __ldg(src + 1024 + tid);
    }
    if (tid == 0) sflag = 0;
    __syncthreads();

    const int tc = __ldg(tn + b);
    int pred_n;
    const float ce = ce_smem(&slog[tid * NCC], tc, &pred_n);
    const float ch = chamfer(pred + (size_t)b * (PP / 2), tgt + (size_t)b * (PP / 2), pred_n, tc);
    float acc = 5.f * ce + ch;

    // Deterministic block tree reduction
    sred[tid] = acc;
    __syncthreads();
#pragma unroll
    for (int s = 64; s > 0; s >>= 1) {
        if (tid < s) sred[tid] += sred[tid + s];
        __syncthreads();
    }

    if (tid == 0) {
        g_partials[blockIdx.x] = sred[0];
        __threadfence();
        unsigned n = atomicAdd(&g_count, 1);
        if (n == NBLK - 1) sflag = 1;
    }
    __syncthreads();

    // Last block: deterministic fixed-order tree over all partials.
    if (sflag) {
        __threadfence();
        volatile float* vp = g_partials;
        sred[tid] = (vp[tid] + vp[tid + 128]) + (vp[tid + 256] + vp[tid + 384]);
        __syncthreads();
#pragma unroll
        for (int s = 64; s > 0; s >>= 1) {
            if (tid < s) sred[tid] += sred[tid + s];
            __syncthreads();
        }
        if (tid == 0) {
            out[0] = sred[0] * (1.0f / (float)NB);
            g_count = 0;   // reset for next graph replay
        }
    }
}

extern "C" void kernel_launch(void* const* d_in, const int* in_sizes, int n_in,
                              void* d_out, int out_size) {
    const float*  pole_logits = (const float*)d_in[0];
    const float*  zero_logits = (const float*)d_in[1];
    const float4* poles       = (const float4*)d_in[2];
    const float4* zeros       = (const float4*)d_in[3];
    const float4* tpoles      = (const float4*)d_in[4];
    const float4* tzeros      = (const float4*)d_in[5];
    const int*    tnp         = (const int*)d_in[6];
    const int*    tnz         = (const int*)d_in[7];

    loss_kernel<<<NBLK, 128>>>(pole_logits, zero_logits, poles, zeros,
                               tpoles, tzeros, tnp, tnz, (float*)d_out);
}